// round 1
// baseline (speedup 1.0000x reference)
#include <cuda_runtime.h>
#include <math.h>
#include <stdint.h>

#define NB    8192      // batch
#define DK    768       // key dim
#define DIM   768       // embedding dim
#define POOL  30
#define PLEN  20
#define TOPK  5
#define HALF  10        // PLEN/2

// Scratch (no allocation allowed): normalized keys + selected indices.
__device__ float g_nk[POOL * DK];
__device__ int   g_idx[NB * TOPK];

// ---------------------------------------------------------------------------
// Kernel 0: normalize K rows. 30 warps, one warp per pool row.
// ---------------------------------------------------------------------------
__global__ void norm_kernel(const float* __restrict__ K) {
    int w    = threadIdx.x >> 5;
    int lane = threadIdx.x & 31;
    if (w >= POOL) return;

    const float4* k4 = reinterpret_cast<const float4*>(K) + w * (DK / 4);
    float4 v[6];
    float ss = 0.0f;
#pragma unroll
    for (int j = 0; j < 6; j++) {
        v[j] = __ldg(k4 + j * 32 + lane);
        ss += v[j].x * v[j].x + v[j].y * v[j].y + v[j].z * v[j].z + v[j].w * v[j].w;
    }
#pragma unroll
    for (int off = 16; off; off >>= 1)
        ss += __shfl_xor_sync(0xFFFFFFFFu, ss, off);

    float inv = 1.0f / sqrtf(fmaxf(ss, 1e-24f));   // matches max(norm,1e-12)
    float4* o = reinterpret_cast<float4*>(g_nk) + w * (DK / 4);
#pragma unroll
    for (int j = 0; j < 6; j++) {
        float4 r = v[j];
        r.x *= inv; r.y *= inv; r.z *= inv; r.w *= inv;
        o[j * 32 + lane] = r;
    }
}

// ---------------------------------------------------------------------------
// Kernel 1: cosine-sim top-5. One warp handles 4 rows; block = 4 warps = 16 rows.
// g_nk (92 KB) stays hot in L1 via __ldg. Per k: 6x LDG.128 feed 4 accumulators.
// ---------------------------------------------------------------------------
__global__ __launch_bounds__(128, 4) void topk_kernel(const float* __restrict__ xq) {
    int lane  = threadIdx.x & 31;
    int wInB  = threadIdx.x >> 5;                 // warp in block (0..3)
    int gwarp = blockIdx.x * 4 + wInB;            // global warp id
    int row0  = gwarp * 4;                        // 4 rows per warp

    __shared__ float s_sims[16][POOL + 2];        // [localRow][k], padded

    const float4* q4 = reinterpret_cast<const float4*>(xq);
    float4 q[4][6];
#pragma unroll
    for (int r = 0; r < 4; r++) {
        const float4* src = q4 + (size_t)(row0 + r) * (DK / 4);
#pragma unroll
        for (int j = 0; j < 6; j++)
            q[r][j] = __ldg(src + j * 32 + lane);
    }

    const float4* nk4 = reinterpret_cast<const float4*>(g_nk);
    for (int k = 0; k < POOL; k++) {
        float a0 = 0.f, a1 = 0.f, a2 = 0.f, a3 = 0.f;
        const float4* nk = nk4 + k * (DK / 4);
#pragma unroll
        for (int j = 0; j < 6; j++) {
            float4 n = __ldg(nk + j * 32 + lane);
            a0 += q[0][j].x * n.x + q[0][j].y * n.y + q[0][j].z * n.z + q[0][j].w * n.w;
            a1 += q[1][j].x * n.x + q[1][j].y * n.y + q[1][j].z * n.z + q[1][j].w * n.w;
            a2 += q[2][j].x * n.x + q[2][j].y * n.y + q[2][j].z * n.z + q[2][j].w * n.w;
            a3 += q[3][j].x * n.x + q[3][j].y * n.y + q[3][j].z * n.z + q[3][j].w * n.w;
        }
#pragma unroll
        for (int off = 16; off; off >>= 1) {
            a0 += __shfl_xor_sync(0xFFFFFFFFu, a0, off);
            a1 += __shfl_xor_sync(0xFFFFFFFFu, a1, off);
            a2 += __shfl_xor_sync(0xFFFFFFFFu, a2, off);
            a3 += __shfl_xor_sync(0xFFFFFFFFu, a3, off);
        }
        if (lane == 0) {
            s_sims[wInB * 4 + 0][k] = a0;
            s_sims[wInB * 4 + 1][k] = a1;
            s_sims[wInB * 4 + 2][k] = a2;
            s_sims[wInB * 4 + 3][k] = a3;
        }
    }
    __syncthreads();

    // Serial top-5 per row; threads 0..15 each own one local row.
    if (threadIdx.x < 16) {
        int lr  = threadIdx.x;
        int row = blockIdx.x * 16 + lr;
        unsigned used = 0;
#pragma unroll
        for (int t = 0; t < TOPK; t++) {
            float best = -3.4e38f;
            int   bi   = 0;
            for (int k = 0; k < POOL; k++) {
                if ((used >> k) & 1u) continue;
                float v = s_sims[lr][k];
                if (v > best) { best = v; bi = k; }   // strict > => smallest index on ties
            }
            used |= (1u << bi);
            g_idx[row * TOPK + t] = bi;
        }
    }
}

// ---------------------------------------------------------------------------
// Kernel 2: gather. Block (t=blockIdx.x in 0..4, b=blockIdx.y) copies prompt
// p[idx[b][t]] (20x768 fp32 = 60 KB): first half -> Ek region, second -> Ev.
// Both destination regions are fully contiguous (10*768 floats each).
// ---------------------------------------------------------------------------
__global__ __launch_bounds__(256) void gather_kernel(const float* __restrict__ p,
                                                     float* __restrict__ out) {
    int t = blockIdx.x;        // 0..4
    int b = blockIdx.y;        // 0..NB-1
    int k = g_idx[b * TOPK + t];

    const float4* src  = reinterpret_cast<const float4*>(p) + (size_t)k * (PLEN * DIM / 4);
    float4*       out4 = reinterpret_cast<float4*>(out);

    const size_t base0 = ((size_t)b * (TOPK * HALF) + (size_t)t * HALF) * (DIM / 4);
    const size_t base1 = ((size_t)(NB + b) * (TOPK * HALF) + (size_t)t * HALF) * (DIM / 4);
    const int    halfN = HALF * DIM / 4;   // 1920 float4 per half

#pragma unroll 5
    for (int i = threadIdx.x; i < PLEN * DIM / 4; i += 256) {
        float4 v = __ldg(src + i);
        if (i < halfN) out4[base0 + i] = v;
        else           out4[base1 + (i - halfN)] = v;
    }
}

// ---------------------------------------------------------------------------
extern "C" void kernel_launch(void* const* d_in, const int* in_sizes, int n_in,
                              void* d_out, int out_size) {
    const float* xq = (const float*)d_in[0];   // x_query [8192,768]
    // d_in[1] = x (unused)
    const float* K  = (const float*)d_in[2];   // [30,768]
    const float* p  = (const float*)d_in[3];   // [30,20,768]
    float*       out = (float*)d_out;          // [2,8192,50,768]

    norm_kernel<<<1, 960>>>(K);
    topk_kernel<<<NB / 16, 128>>>(xq);
    gather_kernel<<<dim3(TOPK, NB), 256>>>(p, out);
}